// round 13
// baseline (speedup 1.0000x reference)
#include <cuda_runtime.h>
#include <cuda_bf16.h>

#define DIMC 256
#define HWD  56
#define NBLK 1568   // 32 images * 49 spatial blocks
#define NT   512    // threads per CTA (16 warps)

// ---------------- device weight scratch (bf16) ----------------
__device__ __align__(16) __nv_bfloat16 g_W1B[256 * 1024]; // [K=256][N=1024]
__device__ __align__(16) __nv_bfloat16 g_W2B[1024 * 256]; // [K=1024][N=256]

__global__ void convert_weights(const float* __restrict__ w1,
                                const float* __restrict__ w2) {
    int id = blockIdx.x * blockDim.x + threadIdx.x;
    if (id < 256 * 1024) {
        g_W1B[id] = __float2bfloat16(w1[id]);
        g_W2B[id] = __float2bfloat16(w2[id]);
    }
}

// ---------------- smem layout (bytes) ----------------
// Y    : bf16 [64][264] = 33792
// W1c  : bf16 [256][136] = 69632   (conv alias: patch 2 x 16x14x40 f32; zs f32 64x261)
// W2c  : bf16 [128][264] = 67584   (conv alias: dws f32 + wpk float2)
// Hc   : bf16 [64][136]  = 17408
#define Y_OFF      0
#define Y_STRIDE   264
#define W1C_OFF    33792
#define W1C_STRIDE 136
#define W2C_OFF    103424
#define W2C_STRIDE 264
#define HC_OFF     171008
#define HC_STRIDE  136
#define B1C_OFF    188416
#define DWB_OFF    188928
#define LNW_OFF    189952
#define LNB_OFF    190976
#define RS_OFF     192000   // 16 warps x 64 pos f32 = 4096
#define RQ_OFF     196096   // 4096
#define SMEM_TOTAL 200192

// conv scratch (aliases W1c/W2c regions, dead before MLP staging)
#define PATCH_OFF   33792           // 2 buffers of 16ch x 14r x 40c f32
#define PATCH_BYTES 35840
#define PATCH_FLOATS 8960
#define DWS_OFF    105472           // 256*49 f32 = 50176
#define WPK_OFF    155648           // 16 x 50 float2 = 6400 (ends 162048)

typedef unsigned long long ull;

__device__ __forceinline__ unsigned smem_u32(const void* p) {
    return (unsigned)__cvta_generic_to_shared(p);
}
__device__ __forceinline__ void cp4z(unsigned dst, const void* src, int sz) {
    asm volatile("cp.async.ca.shared.global [%0], [%1], 4, %2;"
                 :: "r"(dst), "l"(src), "r"(sz));
}
__device__ __forceinline__ void cp16(unsigned dst, const void* src) {
    asm volatile("cp.async.cg.shared.global [%0], [%1], 16;"
                 :: "r"(dst), "l"(src));
}
#define CP_COMMIT() asm volatile("cp.async.commit_group;" ::: "memory")
#define CP_WAIT(n)  asm volatile("cp.async.wait_group %0;" :: "n"(n) : "memory")

__device__ __forceinline__ ull pk2(float lo, float hi) {
    ull r; asm("mov.b64 %0, {%1, %2};" : "=l"(r) : "f"(lo), "f"(hi)); return r;
}
__device__ __forceinline__ void upk2(float& lo, float& hi, ull v) {
    asm("mov.b64 {%0, %1}, %2;" : "=f"(lo), "=f"(hi) : "l"(v));
}
__device__ __forceinline__ void ffma2(ull& d, ull a, ull b) {
    asm("fma.rn.f32x2 %0, %1, %2, %0;" : "+l"(d) : "l"(a), "l"(b));
}

__device__ __forceinline__ void ldsm4(unsigned r[4], unsigned addr) {
    asm volatile("ldmatrix.sync.aligned.m8n8.x4.shared.b16 {%0,%1,%2,%3}, [%4];"
                 : "=r"(r[0]), "=r"(r[1]), "=r"(r[2]), "=r"(r[3]) : "r"(addr));
}
__device__ __forceinline__ void ldsm4t(unsigned r[4], unsigned addr) {
    asm volatile("ldmatrix.sync.aligned.m8n8.x4.trans.shared.b16 {%0,%1,%2,%3}, [%4];"
                 : "=r"(r[0]), "=r"(r[1]), "=r"(r[2]), "=r"(r[3]) : "r"(addr));
}
__device__ __forceinline__ void mma16816(float d[4], const unsigned a[4],
                                         unsigned b0, unsigned b1) {
    asm volatile(
        "mma.sync.aligned.m16n8k16.row.col.f32.bf16.bf16.f32 "
        "{%0,%1,%2,%3}, {%4,%5,%6,%7}, {%8,%9}, {%0,%1,%2,%3};"
        : "+f"(d[0]), "+f"(d[1]), "+f"(d[2]), "+f"(d[3])
        : "r"(a[0]), "r"(a[1]), "r"(a[2]), "r"(a[3]), "r"(b0), "r"(b1));
}
__device__ __forceinline__ float gelu_f(float v) {
    float u = 0.7978845608028654f * (v + 0.044715f * v * v * v);
    float th;
    asm("tanh.approx.f32 %0, %1;" : "=f"(th) : "f"(u));
    return 0.5f * v * (1.0f + th);
}

// stage W1 chunk [256 x 128] columns nc*128.. into W1c (stride 136)
__device__ __forceinline__ void stage_w1(unsigned W1base, int nc, int t) {
    const uint4* s1 = (const uint4*)g_W1B;
    for (int i = t; i < 4096; i += NT) {
        int k = i >> 4, q = i & 15;
        cp16(W1base + (k * 17 + q) * 16, s1 + k * 128 + nc * 16 + q);
    }
}
// stage W2 chunk [128 x 256] rows nc*128.. into W2c (stride 264)
__device__ __forceinline__ void stage_w2(unsigned W2base, int nc, int t) {
    const uint4* s2 = (const uint4*)g_W2B;
    for (int i = t; i < 4096; i += NT) {
        int k = i >> 5, q = i & 31;
        cp16(W2base + (k * 33 + q) * 16, s2 + (size_t)(nc * 128 + k) * 32 + q);
    }
}

__global__ __launch_bounds__(NT, 1)
void block_kernel(const float* __restrict__ x, const int* __restrict__ mask,
                  const float* __restrict__ dw_w, const float* __restrict__ dw_b,
                  const float* __restrict__ ln_w, const float* __restrict__ ln_b,
                  const float* __restrict__ b1, const float* __restrict__ b2,
                  const float* __restrict__ gamma, float* __restrict__ out) {
    extern __shared__ char sm[];
    const int t   = threadIdx.x;
    const int blk = blockIdx.x;
    const int b   = blk / 49;
    const int s   = blk % 49;
    const int h0  = (s / 7) * 8;
    const int w0  = (s % 7) * 8;
    const float* xb = x   + (size_t)b * DIMC * HWD * HWD;
    float*       ob = out + (size_t)b * DIMC * HWD * HWD;

    if (mask[blk] == 0) {
        for (int i = t; i < 4096; i += NT) {
            int c = i >> 4, sub = i & 15;
            int rr = sub >> 1, half = sub & 1;
            size_t g = (size_t)(c * HWD + h0 + rr) * HWD + w0;
            ((float4*)(ob + g))[half] = ((const float4*)(xb + g))[half];
        }
        return;
    }

    __nv_bfloat16* Ys = (__nv_bfloat16*)(sm + Y_OFF);
    float* patchF = (float*)(sm + PATCH_OFF);
    float* dws    = (float*)(sm + DWS_OFF);
    float* b1c    = (float*)(sm + B1C_OFF);
    float* dwb_s  = (float*)(sm + DWB_OFF);
    float* lnw_s  = (float*)(sm + LNW_OFF);
    float* lnb_s  = (float*)(sm + LNB_OFF);
    float* rS     = (float*)(sm + RS_OFF);
    float* rQ     = (float*)(sm + RQ_OFF);

    const int lane = t & 31, wrp = t >> 5;

    // -------- precompute stage-invariant patch-staging offsets --------------
    int soff[7], sdst[7], ssz[7];
#pragma unroll
    for (int k = 0; k < 7; k++) {
        int pos = lane + k * 32;
        int rr  = pos / 14, cw = pos - rr * 14;
        int hh  = h0 - 3 + rr, ww = w0 - 3 + cw;
        bool ok = ((unsigned)hh < 56u) && ((unsigned)ww < 56u);
        soff[k] = ok ? hh * HWD + ww : 0;
        ssz[k]  = ok ? 4 : 0;
        sdst[k] = (rr * 40 + cw) * 4;
    }

    // -------- prologue: async-stage dw weights + patch(0); plain consts ------
    const unsigned dwsBase   = smem_u32(dws);
    const unsigned patchBase = smem_u32(patchF);
    {
        const uint4* src = (const uint4*)dw_w;   // 3136 uint4
        for (int i = t; i < 3136; i += NT)
            cp16(dwsBase + i * 16, src + i);
        if (t < 256) {
            dwb_s[t] = dw_b[t];
            lnw_s[t] = ln_w[t];
            lnb_s[t] = ln_b[t];
        }
    }
    const float* xch0 = xb + (size_t)wrp * (HWD * HWD);   // channel wrp plane
    {
        unsigned pb = patchBase + wrp * (14 * 40 * 4);    // buf 0
#pragma unroll
        for (int k = 0; k < 6; k++) cp4z(pb + sdst[k], xch0 + soff[k], ssz[k]);
        if (lane < 4) cp4z(pb + sdst[6], xch0 + soff[6], ssz[6]);
    }
    CP_COMMIT();

    // -------- conv: 16 stages, warp=channel, thread=(row, colpair) ----------
    const int row = lane >> 2;          // 0..7
    const int c0  = (lane & 3) * 2;     // 0,2,4,6
    const int p0  = row * 8 + c0;
    float sum0 = 0.f, ssq0 = 0.f, sum1 = 0.f, ssq1 = 0.f;

    ull* wpk = (ull*)(sm + WPK_OFF);

    for (int st = 0; st < 16; st++) {
        __syncthreads();   // compute(st-1) fully done -> safe to refill its buffer
        if (st < 15) {
            unsigned pb = patchBase + ((st + 1) & 1) * PATCH_BYTES
                        + wrp * (14 * 40 * 4);
            const float* xsrc = xch0 + (size_t)(st + 1) * 16 * (HWD * HWD);
#pragma unroll
            for (int k = 0; k < 6; k++) cp4z(pb + sdst[k], xsrc + soff[k], ssz[k]);
            if (lane < 4) cp4z(pb + sdst[6], xsrc + soff[6], ssz[6]);
            CP_COMMIT();
            CP_WAIT(1);    // patch(st) ready; patch(st+1) in flight
        } else {
            CP_WAIT(0);
        }
        __syncthreads();

        const int chg = st * 16 + wrp;
        // pack this warp's channel weights as {w,w} (warp-private buffer)
        {
            const float* wsrc = dws + chg * 49;
            ull* wdst = wpk + wrp * 50;
            if (lane < 25) {
                float wv = wsrc[lane];
                wdst[lane] = pk2(wv, wv);
                if (lane < 24) {
                    float wv2 = wsrc[25 + lane];
                    wdst[25 + lane] = pk2(wv2, wv2);
                }
            }
            __syncwarp();
        }
        const ull* wp = wpk + wrp * 50;
        const float* pch = patchF + (st & 1) * PATCH_FLOATS + wrp * (14 * 40);
        float bias = dwb_s[chg];
        ull acc = pk2(bias, bias);
#pragma unroll
        for (int kh = 0; kh < 7; kh++) {
            const float* pr = pch + (row + kh) * 40 + c0;   // 8B aligned (c0 even)
            ull e0 = *(const ull*)(pr);       // {v0,v1}
            ull e2 = *(const ull*)(pr + 2);   // {v2,v3}
            ull e4 = *(const ull*)(pr + 4);   // {v4,v5}
            ull e6 = *(const ull*)(pr + 6);   // {v6,v7}
            float v0, v1, v2, v3, v4, v5, v6, v7;
            upk2(v0, v1, e0); upk2(v2, v3, e2);
            upk2(v4, v5, e4); upk2(v6, v7, e6);
            ffma2(acc, e0,          wp[kh * 7 + 0]);
            ffma2(acc, pk2(v1, v2), wp[kh * 7 + 1]);
            ffma2(acc, e2,          wp[kh * 7 + 2]);
            ffma2(acc, pk2(v3, v4), wp[kh * 7 + 3]);
            ffma2(acc, e4,          wp[kh * 7 + 4]);
            ffma2(acc, pk2(v5, v6), wp[kh * 7 + 5]);
            ffma2(acc, e6,          wp[kh * 7 + 6]);
        }
        float o0, o1;
        upk2(o0, o1, acc);
        sum0 += o0; ssq0 += o0 * o0;
        sum1 += o1; ssq1 += o1 * o1;
        Ys[p0 * Y_STRIDE + chg]       = __float2bfloat16(o0);
        Ys[(p0 + 1) * Y_STRIDE + chg] = __float2bfloat16(o1);
    }

    rS[wrp * 64 + p0]     = sum0;
    rS[wrp * 64 + p0 + 1] = sum1;
    rQ[wrp * 64 + p0]     = ssq0;
    rQ[wrp * 64 + p0 + 1] = ssq1;
    __syncthreads();   // conv fully done: patch/dws/wpk aliases dead

    // -------- prefetch MLP chunk 0 (overlaps with LayerNorm below) ----------
    __nv_bfloat16* W1c = (__nv_bfloat16*)(sm + W1C_OFF);
    __nv_bfloat16* W2c = (__nv_bfloat16*)(sm + W2C_OFF);
    __nv_bfloat16* Hcn = (__nv_bfloat16*)(sm + HC_OFF);
    const unsigned W1base = smem_u32(W1c);
    const unsigned W2base = smem_u32(W2c);
    stage_w1(W1base, 0, t);
    CP_COMMIT();
    stage_w2(W2base, 0, t);
    CP_COMMIT();
    // invariant entering chunk nc: pending groups = [W1(nc), W2(nc)]

    // -------- LayerNorm (thread owns 16 channels x 2 positions) -------------
    {
        float S0 = 0.f, Q0 = 0.f, S1 = 0.f, Q1 = 0.f;
#pragma unroll
        for (int wq = 0; wq < 16; wq++) {
            S0 += rS[wq * 64 + p0];     Q0 += rQ[wq * 64 + p0];
            S1 += rS[wq * 64 + p0 + 1]; Q1 += rQ[wq * 64 + p0 + 1];
        }
        float mu0 = S0 * (1.f / 256.f);
        float mu1 = S1 * (1.f / 256.f);
        float rstd0 = rsqrtf(fmaxf(Q0 * (1.f / 256.f) - mu0 * mu0, 0.f) + 1e-6f);
        float rstd1 = rsqrtf(fmaxf(Q1 * (1.f / 256.f) - mu1 * mu1, 0.f) + 1e-6f);
#pragma unroll 4
        for (int st = 0; st < 16; st++) {
            int ch = st * 16 + wrp;
            float lw = lnw_s[ch], lb = lnb_s[ch];
            float y0 = __bfloat162float(Ys[p0 * Y_STRIDE + ch]);
            float y1 = __bfloat162float(Ys[(p0 + 1) * Y_STRIDE + ch]);
            y0 = (y0 - mu0) * rstd0 * lw + lb;
            y1 = (y1 - mu1) * rstd1 * lw + lb;
            Ys[p0 * Y_STRIDE + ch]       = __float2bfloat16(y0);
            Ys[(p0 + 1) * Y_STRIDE + ch] = __float2bfloat16(y1);
        }
    }

    // ---------------- MLP: pipelined weight staging (4M x 4N warps) ---------
    const int wm = wrp & 3, wn = wrp >> 2;
    const int m0 = wm * 16;
    const unsigned Ybase = smem_u32(Ys);
    const unsigned Hbase = smem_u32(Hcn);
    const unsigned aOffY = Ybase + (m0 + (lane & 15)) * (Y_STRIDE * 2) + ((lane >> 4) << 4);
    const unsigned aOffH = Hbase + (m0 + (lane & 15)) * (HC_STRIDE * 2) + ((lane >> 4) << 4);

    float accZ[8][4];
#pragma unroll
    for (int i = 0; i < 8; i++)
#pragma unroll
        for (int q = 0; q < 4; q++) accZ[i][q] = 0.f;

    for (int nc = 0; nc < 8; nc++) {
        CP_WAIT(1);                      // W1(nc) complete (W2(nc) may be pending)
        if (t < 128) b1c[t] = b1[nc * 128 + t];
        __syncthreads();                 // W1 + b1c (+Ys on nc=0) visible to all

        // GEMM1: H[64,128] = Y[64,256] @ W1c[256,128]; warp tile 16x32
        float acc1[4][4];
#pragma unroll
        for (int i = 0; i < 4; i++)
#pragma unroll
            for (int q = 0; q < 4; q++) acc1[i][q] = 0.f;

#pragma unroll 4
        for (int kk = 0; kk < 256; kk += 16) {
            unsigned a[4];
            ldsm4(a, aOffY + kk * 2);
#pragma unroll
            for (int q = 0; q < 2; q++) {
                unsigned bq[4];
                ldsm4t(bq, W1base + (kk + (lane & 15)) * (W1C_STRIDE * 2)
                                 + (wn * 32 + q * 16) * 2 + ((lane >> 4) << 4));
                mma16816(acc1[2 * q],     a, bq[0], bq[1]);
                mma16816(acc1[2 * q + 1], a, bq[2], bq[3]);
            }
        }
        __syncthreads();                 // all warps done reading W1 buffer
        if (nc < 7) { stage_w1(W1base, nc + 1, t); CP_COMMIT(); }  // overlaps GELU+G2

        // bias + GELU + pack bf16 into Hc
#pragma unroll
        for (int q = 0; q < 4; q++) {
            int cc0 = wn * 32 + q * 8 + 2 * (lane & 3);
            int r   = m0 + (lane >> 2);
            float f0 = gelu_f(acc1[q][0] + b1c[cc0]);
            float f1 = gelu_f(acc1[q][1] + b1c[cc0 + 1]);
            float f2 = gelu_f(acc1[q][2] + b1c[cc0]);
            float f3 = gelu_f(acc1[q][3] + b1c[cc0 + 1]);
            __nv_bfloat162 h01, h23;
            h01.x = __float2bfloat16(f0); h01.y = __float2bfloat16(f1);
            h23.x = __float2bfloat16(f2); h23.y = __float2bfloat16(f3);
            *(__nv_bfloat162*)&Hcn[r * HC_STRIDE + cc0]       = h01;
            *(__nv_bfloat162*)&Hcn[(r + 8) * HC_STRIDE + cc0] = h23;
        }
        if (nc < 7) { CP_WAIT(1); } else { CP_WAIT(0); }   // W2(nc) complete
        __syncthreads();                 // Hc + W2 visible

        // GEMM2: Z[64,256] += H[64,128] @ W2c[128,256]; warp tile 16x64
#pragma unroll 2
        for (int kk = 0; kk < 128; kk += 16) {
            unsigned a[4];
            ldsm4(a, aOffH + kk * 2);
#pragma unroll
            for (int q = 0; q < 4; q++) {
                unsigned bq[4];
                ldsm4t(bq, W2base + (kk + (lane & 15)) * (W2C_STRIDE * 2)
                                 + (wn * 64 + q * 16) * 2 + ((lane >> 4) << 4));
                mma16816(accZ[2 * q],     a, bq[0], bq[1]);
                mma16816(accZ[2 * q + 1], a, bq[2], bq[3]);
            }
        }
        __syncthreads();                 // W2 buffer + Hc free
        if (nc < 7) { stage_w2(W2base, nc + 1, t); CP_COMMIT(); }  // overlaps next G1
    }

    // dump Z to smem (transpose buffer, stride 261) — zs aliases W1c (free now)
    float* zs = (float*)(sm + W1C_OFF);
#pragma unroll
    for (int q = 0; q < 8; q++) {
        int cc0 = wn * 64 + q * 8 + 2 * (lane & 3);
        int r   = m0 + (lane >> 2);
        zs[r * 261 + cc0]           = accZ[q][0];
        zs[r * 261 + cc0 + 1]       = accZ[q][1];
        zs[(r + 8) * 261 + cc0]     = accZ[q][2];
        zs[(r + 8) * 261 + cc0 + 1] = accZ[q][3];
    }
    __syncthreads();

    // epilogue: out = x + (z + b2) * gamma, float4-vectorized
    for (int i = t; i < 4096; i += NT) {
        int c = i >> 4, sub = i & 15;
        int rr = sub >> 1, half = sub & 1;
        int pp = rr * 8 + half * 4;
        float gm = __ldg(gamma + c), bb = __ldg(b2 + c);
        float4 z4;
        z4.x = (zs[(pp + 0) * 261 + c] + bb) * gm;
        z4.y = (zs[(pp + 1) * 261 + c] + bb) * gm;
        z4.z = (zs[(pp + 2) * 261 + c] + bb) * gm;
        z4.w = (zs[(pp + 3) * 261 + c] + bb) * gm;
        size_t g = (size_t)(c * HWD + h0 + rr) * HWD + w0;
        float4 xv = ((const float4*)(xb + g))[half];
        xv.x += z4.x; xv.y += z4.y; xv.z += z4.z; xv.w += z4.w;
        ((float4*)(ob + g))[half] = xv;
    }
}

extern "C" void kernel_launch(void* const* d_in, const int* in_sizes, int n_in,
                              void* d_out, int out_size) {
    const float* x     = (const float*)d_in[0];
    const int*   mask  = (const int*)d_in[1];
    const float* dw_w  = (const float*)d_in[2];
    const float* dw_b  = (const float*)d_in[3];
    const float* ln_w  = (const float*)d_in[4];
    const float* ln_b  = (const float*)d_in[5];
    const float* w1    = (const float*)d_in[6];
    const float* b1    = (const float*)d_in[7];
    const float* w2    = (const float*)d_in[8];
    const float* b2    = (const float*)d_in[9];
    const float* gamma = (const float*)d_in[10];
    float* out = (float*)d_out;

    convert_weights<<<512, 512>>>(w1, w2);

    cudaFuncSetAttribute(block_kernel,
                         cudaFuncAttributeMaxDynamicSharedMemorySize, SMEM_TOTAL);
    block_kernel<<<NBLK, NT, SMEM_TOTAL>>>(x, mask, dw_w, dw_b, ln_w, ln_b,
                                           b1, b2, gamma, out);
}

// round 16
// speedup vs baseline: 1.5210x; 1.5210x over previous
#include <cuda_runtime.h>
#include <cuda_bf16.h>

#define DIMC 256
#define HWD  56
#define NBLK 1568   // 32 images * 49 spatial blocks
#define NT   512    // threads per CTA (16 warps)

// ---------------- device weight scratch (bf16) ----------------
__device__ __align__(16) __nv_bfloat16 g_W1B[256 * 1024]; // [K=256][N=1024]
__device__ __align__(16) __nv_bfloat16 g_W2B[1024 * 256]; // [K=1024][N=256]

__global__ void convert_weights(const float* __restrict__ w1,
                                const float* __restrict__ w2) {
    int id = blockIdx.x * blockDim.x + threadIdx.x;
    if (id < 256 * 1024) {
        g_W1B[id] = __float2bfloat16(w1[id]);
        g_W2B[id] = __float2bfloat16(w2[id]);
    }
}

// ---------------- smem layout (bytes) ----------------
// Y    : bf16 [64][264] = 33792
// W1c  : bf16 [256][136] = 69632   (conv alias: patch 2 x 16x14x40 f32; zs f32 64x261)
// W2c  : bf16 [128][264] = 67584   (conv alias: dws f32 + wpk float2)
// Hc   : bf16 [64][136]  = 17408
#define Y_OFF      0
#define Y_STRIDE   264
#define W1C_OFF    33792
#define W1C_STRIDE 136
#define W2C_OFF    103424
#define W2C_STRIDE 264
#define HC_OFF     171008
#define HC_STRIDE  136
#define B1C_OFF    188416
#define DWB_OFF    188928
#define LNW_OFF    189952
#define LNB_OFF    190976
#define RS_OFF     192000   // 16 warps x 64 pos f32 = 4096
#define RQ_OFF     196096   // 4096
#define SMEM_TOTAL 200192

// conv scratch (aliases W1c/W2c regions, dead before MLP staging)
#define PATCH_OFF   33792           // 2 buffers of 16ch x 14r x 40c f32
#define PATCH_BYTES 35840
#define PATCH_FLOATS 8960
#define DWS_OFF    105472           // 256*49 f32 = 50176
#define WPK_OFF    155648           // 16 x 50 float2 = 6400 (ends 162048)

typedef unsigned long long ull;

__device__ __forceinline__ unsigned smem_u32(const void* p) {
    return (unsigned)__cvta_generic_to_shared(p);
}
__device__ __forceinline__ void cp4z(unsigned dst, const void* src, int sz) {
    asm volatile("cp.async.ca.shared.global [%0], [%1], 4, %2;"
                 :: "r"(dst), "l"(src), "r"(sz));
}
__device__ __forceinline__ void cp16(unsigned dst, const void* src) {
    asm volatile("cp.async.cg.shared.global [%0], [%1], 16;"
                 :: "r"(dst), "l"(src));
}
#define CP_COMMIT() asm volatile("cp.async.commit_group;" ::: "memory")
#define CP_WAIT(n)  asm volatile("cp.async.wait_group %0;" :: "n"(n) : "memory")

__device__ __forceinline__ ull pk2(float lo, float hi) {
    ull r; asm("mov.b64 %0, {%1, %2};" : "=l"(r) : "f"(lo), "f"(hi)); return r;
}
__device__ __forceinline__ void upk2(float& lo, float& hi, ull v) {
    asm("mov.b64 {%0, %1}, %2;" : "=f"(lo), "=f"(hi) : "l"(v));
}
__device__ __forceinline__ void ffma2(ull& d, ull a, ull b) {
    asm("fma.rn.f32x2 %0, %1, %2, %0;" : "+l"(d) : "l"(a), "l"(b));
}

__device__ __forceinline__ void ldsm4(unsigned r[4], unsigned addr) {
    asm volatile("ldmatrix.sync.aligned.m8n8.x4.shared.b16 {%0,%1,%2,%3}, [%4];"
                 : "=r"(r[0]), "=r"(r[1]), "=r"(r[2]), "=r"(r[3]) : "r"(addr));
}
__device__ __forceinline__ void ldsm4t(unsigned r[4], unsigned addr) {
    asm volatile("ldmatrix.sync.aligned.m8n8.x4.trans.shared.b16 {%0,%1,%2,%3}, [%4];"
                 : "=r"(r[0]), "=r"(r[1]), "=r"(r[2]), "=r"(r[3]) : "r"(addr));
}
__device__ __forceinline__ void mma16816(float d[4], const unsigned a[4],
                                         unsigned b0, unsigned b1) {
    asm volatile(
        "mma.sync.aligned.m16n8k16.row.col.f32.bf16.bf16.f32 "
        "{%0,%1,%2,%3}, {%4,%5,%6,%7}, {%8,%9}, {%0,%1,%2,%3};"
        : "+f"(d[0]), "+f"(d[1]), "+f"(d[2]), "+f"(d[3])
        : "r"(a[0]), "r"(a[1]), "r"(a[2]), "r"(a[3]), "r"(b0), "r"(b1));
}
__device__ __forceinline__ float gelu_f(float v) {
    float u = 0.7978845608028654f * (v + 0.044715f * v * v * v);
    float th;
    asm("tanh.approx.f32 %0, %1;" : "=f"(th) : "f"(u));
    return 0.5f * v * (1.0f + th);
}

// stage W1 chunk [256 x 128] columns nc*128.. into W1c (stride 136)
__device__ __forceinline__ void stage_w1(unsigned W1base, int nc, int t) {
    const uint4* s1 = (const uint4*)g_W1B;
    for (int i = t; i < 4096; i += NT) {
        int k = i >> 4, q = i & 15;
        cp16(W1base + (k * 17 + q) * 16, s1 + k * 128 + nc * 16 + q);
    }
}
// stage W2 chunk [128 x 256] rows nc*128.. into W2c (stride 264)
__device__ __forceinline__ void stage_w2(unsigned W2base, int nc, int t) {
    const uint4* s2 = (const uint4*)g_W2B;
    for (int i = t; i < 4096; i += NT) {
        int k = i >> 5, q = i & 31;
        cp16(W2base + (k * 33 + q) * 16, s2 + (size_t)(nc * 128 + k) * 32 + q);
    }
}

__global__ __launch_bounds__(NT, 1)
void block_kernel(const float* __restrict__ x, const int* __restrict__ mask,
                  const float* __restrict__ dw_w, const float* __restrict__ dw_b,
                  const float* __restrict__ ln_w, const float* __restrict__ ln_b,
                  const float* __restrict__ b1, const float* __restrict__ b2,
                  const float* __restrict__ gamma, float* __restrict__ out) {
    extern __shared__ char sm[];
    const int t   = threadIdx.x;
    const int blk = blockIdx.x;
    const int b   = blk / 49;
    const int s   = blk % 49;
    const int h0  = (s / 7) * 8;
    const int w0  = (s % 7) * 8;
    const float* xb = x   + (size_t)b * DIMC * HWD * HWD;
    float*       ob = out + (size_t)b * DIMC * HWD * HWD;

    if (mask[blk] == 0) {
        for (int i = t; i < 4096; i += NT) {
            int c = i >> 4, sub = i & 15;
            int rr = sub >> 1, half = sub & 1;
            size_t g = (size_t)(c * HWD + h0 + rr) * HWD + w0;
            ((float4*)(ob + g))[half] = ((const float4*)(xb + g))[half];
        }
        return;
    }

    __nv_bfloat16* Ys = (__nv_bfloat16*)(sm + Y_OFF);
    float* patchF = (float*)(sm + PATCH_OFF);
    float* dws    = (float*)(sm + DWS_OFF);
    float* b1c    = (float*)(sm + B1C_OFF);
    float* dwb_s  = (float*)(sm + DWB_OFF);
    float* lnw_s  = (float*)(sm + LNW_OFF);
    float* lnb_s  = (float*)(sm + LNB_OFF);
    float* rS     = (float*)(sm + RS_OFF);
    float* rQ     = (float*)(sm + RQ_OFF);

    const int lane = t & 31, wrp = t >> 5;

    // -------- precompute stage-invariant patch-staging offsets --------------
    int soff[7], sdst[7], ssz[7];
#pragma unroll
    for (int k = 0; k < 7; k++) {
        int pos = lane + k * 32;
        int rr  = pos / 14, cw = pos - rr * 14;
        int hh  = h0 - 3 + rr, ww = w0 - 3 + cw;
        bool ok = ((unsigned)hh < 56u) && ((unsigned)ww < 56u);
        soff[k] = ok ? hh * HWD + ww : 0;
        ssz[k]  = ok ? 4 : 0;
        sdst[k] = (rr * 40 + cw) * 4;
    }

    // -------- prologue: async-stage dw weights + patch(0); plain consts ------
    const unsigned dwsBase   = smem_u32(dws);
    const unsigned patchBase = smem_u32(patchF);
    {
        const uint4* src = (const uint4*)dw_w;   // 3136 uint4
        for (int i = t; i < 3136; i += NT)
            cp16(dwsBase + i * 16, src + i);
        if (t < 256) {
            dwb_s[t] = dw_b[t];
            lnw_s[t] = ln_w[t];
            lnb_s[t] = ln_b[t];
        }
    }
    const float* xch0 = xb + (size_t)wrp * (HWD * HWD);   // channel wrp plane
    {
        unsigned pb = patchBase + wrp * (14 * 40 * 4);    // buf 0
#pragma unroll
        for (int k = 0; k < 6; k++) cp4z(pb + sdst[k], xch0 + soff[k], ssz[k]);
        if (lane < 4) cp4z(pb + sdst[6], xch0 + soff[6], ssz[6]);
    }
    CP_COMMIT();

    // -------- conv: 16 stages, warp=channel, thread=(row, colpair) ----------
    const int row = lane >> 2;          // 0..7
    const int c0  = (lane & 3) * 2;     // 0,2,4,6
    const int p0  = row * 8 + c0;
    float sum0 = 0.f, ssq0 = 0.f, sum1 = 0.f, ssq1 = 0.f;

    ull* wpk = (ull*)(sm + WPK_OFF);

    for (int st = 0; st < 16; st++) {
        __syncthreads();   // compute(st-1) fully done -> safe to refill its buffer
        if (st < 15) {
            unsigned pb = patchBase + ((st + 1) & 1) * PATCH_BYTES
                        + wrp * (14 * 40 * 4);
            const float* xsrc = xch0 + (size_t)(st + 1) * 16 * (HWD * HWD);
#pragma unroll
            for (int k = 0; k < 6; k++) cp4z(pb + sdst[k], xsrc + soff[k], ssz[k]);
            if (lane < 4) cp4z(pb + sdst[6], xsrc + soff[6], ssz[6]);
            CP_COMMIT();
            CP_WAIT(1);    // patch(st) ready; patch(st+1) in flight
        } else {
            CP_WAIT(0);
        }
        __syncthreads();

        const int chg = st * 16 + wrp;
        // pack this warp's channel weights as {w,w} (warp-private buffer)
        {
            const float* wsrc = dws + chg * 49;
            ull* wdst = wpk + wrp * 50;
            if (lane < 25) {
                float wv = wsrc[lane];
                wdst[lane] = pk2(wv, wv);
                if (lane < 24) {
                    float wv2 = wsrc[25 + lane];
                    wdst[25 + lane] = pk2(wv2, wv2);
                }
            }
            __syncwarp();
        }
        const ull* wp = wpk + wrp * 50;
        const float* pch = patchF + (st & 1) * PATCH_FLOATS + wrp * (14 * 40);
        float bias = dwb_s[chg];
        ull acc = pk2(bias, bias);
#pragma unroll
        for (int kh = 0; kh < 7; kh++) {
            const float* pr = pch + (row + kh) * 40 + c0;   // 8B aligned (c0 even)
            ull e0 = *(const ull*)(pr);       // {v0,v1}
            ull e2 = *(const ull*)(pr + 2);   // {v2,v3}
            ull e4 = *(const ull*)(pr + 4);   // {v4,v5}
            ull e6 = *(const ull*)(pr + 6);   // {v6,v7}
            float v0, v1, v2, v3, v4, v5, v6, v7;
            upk2(v0, v1, e0); upk2(v2, v3, e2);
            upk2(v4, v5, e4); upk2(v6, v7, e6);
            ffma2(acc, e0,          wp[kh * 7 + 0]);
            ffma2(acc, pk2(v1, v2), wp[kh * 7 + 1]);
            ffma2(acc, e2,          wp[kh * 7 + 2]);
            ffma2(acc, pk2(v3, v4), wp[kh * 7 + 3]);
            ffma2(acc, e4,          wp[kh * 7 + 4]);
            ffma2(acc, pk2(v5, v6), wp[kh * 7 + 5]);
            ffma2(acc, e6,          wp[kh * 7 + 6]);
        }
        float o0, o1;
        upk2(o0, o1, acc);
        sum0 += o0; ssq0 += o0 * o0;
        sum1 += o1; ssq1 += o1 * o1;
        Ys[p0 * Y_STRIDE + chg]       = __float2bfloat16(o0);
        Ys[(p0 + 1) * Y_STRIDE + chg] = __float2bfloat16(o1);
    }

    rS[wrp * 64 + p0]     = sum0;
    rS[wrp * 64 + p0 + 1] = sum1;
    rQ[wrp * 64 + p0]     = ssq0;
    rQ[wrp * 64 + p0 + 1] = ssq1;
    __syncthreads();   // conv fully done: patch/dws/wpk aliases dead

    // -------- prefetch MLP chunk 0 (overlaps with LayerNorm below) ----------
    __nv_bfloat16* W1c = (__nv_bfloat16*)(sm + W1C_OFF);
    __nv_bfloat16* W2c = (__nv_bfloat16*)(sm + W2C_OFF);
    __nv_bfloat16* Hcn = (__nv_bfloat16*)(sm + HC_OFF);
    const unsigned W1base = smem_u32(W1c);
    const unsigned W2base = smem_u32(W2c);
    stage_w1(W1base, 0, t);
    CP_COMMIT();
    stage_w2(W2base, 0, t);
    CP_COMMIT();
    // invariant entering chunk nc: pending groups = [W1(nc), W2(nc)]

    // -------- LayerNorm (thread owns 16 channels x 2 positions) -------------
    {
        float S0 = 0.f, Q0 = 0.f, S1 = 0.f, Q1 = 0.f;
#pragma unroll
        for (int wq = 0; wq < 16; wq++) {
            S0 += rS[wq * 64 + p0];     Q0 += rQ[wq * 64 + p0];
            S1 += rS[wq * 64 + p0 + 1]; Q1 += rQ[wq * 64 + p0 + 1];
        }
        float mu0 = S0 * (1.f / 256.f);
        float mu1 = S1 * (1.f / 256.f);
        float rstd0 = rsqrtf(fmaxf(Q0 * (1.f / 256.f) - mu0 * mu0, 0.f) + 1e-6f);
        float rstd1 = rsqrtf(fmaxf(Q1 * (1.f / 256.f) - mu1 * mu1, 0.f) + 1e-6f);
#pragma unroll 4
        for (int st = 0; st < 16; st++) {
            int ch = st * 16 + wrp;
            float lw = lnw_s[ch], lb = lnb_s[ch];
            float y0 = __bfloat162float(Ys[p0 * Y_STRIDE + ch]);
            float y1 = __bfloat162float(Ys[(p0 + 1) * Y_STRIDE + ch]);
            y0 = (y0 - mu0) * rstd0 * lw + lb;
            y1 = (y1 - mu1) * rstd1 * lw + lb;
            Ys[p0 * Y_STRIDE + ch]       = __float2bfloat16(y0);
            Ys[(p0 + 1) * Y_STRIDE + ch] = __float2bfloat16(y1);
        }
    }

    // ---------------- MLP: pipelined weight staging (4M x 4N warps) ---------
    const int wm = wrp & 3, wn = wrp >> 2;
    const int m0 = wm * 16;
    const unsigned Ybase = smem_u32(Ys);
    const unsigned Hbase = smem_u32(Hcn);
    const unsigned aOffY = Ybase + (m0 + (lane & 15)) * (Y_STRIDE * 2) + ((lane >> 4) << 4);
    const unsigned aOffH = Hbase + (m0 + (lane & 15)) * (HC_STRIDE * 2) + ((lane >> 4) << 4);

    float accZ[8][4];
#pragma unroll
    for (int i = 0; i < 8; i++)
#pragma unroll
        for (int q = 0; q < 4; q++) accZ[i][q] = 0.f;

    for (int nc = 0; nc < 8; nc++) {
        CP_WAIT(1);                      // W1(nc) complete (W2(nc) may be pending)
        if (t < 128) b1c[t] = b1[nc * 128 + t];
        __syncthreads();                 // W1 + b1c (+Ys on nc=0) visible to all

        // GEMM1: H[64,128] = Y[64,256] @ W1c[256,128]; warp tile 16x32
        float acc1[4][4];
#pragma unroll
        for (int i = 0; i < 4; i++)
#pragma unroll
            for (int q = 0; q < 4; q++) acc1[i][q] = 0.f;

#pragma unroll 4
        for (int kk = 0; kk < 256; kk += 16) {
            unsigned a[4];
            ldsm4(a, aOffY + kk * 2);
#pragma unroll
            for (int q = 0; q < 2; q++) {
                unsigned bq[4];
                ldsm4t(bq, W1base + (kk + (lane & 15)) * (W1C_STRIDE * 2)
                                 + (wn * 32 + q * 16) * 2 + ((lane >> 4) << 4));
                mma16816(acc1[2 * q],     a, bq[0], bq[1]);
                mma16816(acc1[2 * q + 1], a, bq[2], bq[3]);
            }
        }
        __syncthreads();                 // all warps done reading W1 buffer
        if (nc < 7) { stage_w1(W1base, nc + 1, t); CP_COMMIT(); }  // overlaps GELU+G2

        // bias + GELU + pack bf16 into Hc
#pragma unroll
        for (int q = 0; q < 4; q++) {
            int cc0 = wn * 32 + q * 8 + 2 * (lane & 3);
            int r   = m0 + (lane >> 2);
            float f0 = gelu_f(acc1[q][0] + b1c[cc0]);
            float f1 = gelu_f(acc1[q][1] + b1c[cc0 + 1]);
            float f2 = gelu_f(acc1[q][2] + b1c[cc0]);
            float f3 = gelu_f(acc1[q][3] + b1c[cc0 + 1]);
            __nv_bfloat162 h01, h23;
            h01.x = __float2bfloat16(f0); h01.y = __float2bfloat16(f1);
            h23.x = __float2bfloat16(f2); h23.y = __float2bfloat16(f3);
            *(__nv_bfloat162*)&Hcn[r * HC_STRIDE + cc0]       = h01;
            *(__nv_bfloat162*)&Hcn[(r + 8) * HC_STRIDE + cc0] = h23;
        }
        if (nc < 7) { CP_WAIT(1); } else { CP_WAIT(0); }   // W2(nc) complete
        __syncthreads();                 // Hc + W2 visible

        // GEMM2: Z[64,256] += H[64,128] @ W2c[128,256]; warp tile 16x64
#pragma unroll 2
        for (int kk = 0; kk < 128; kk += 16) {
            unsigned a[4];
            ldsm4(a, aOffH + kk * 2);
#pragma unroll
            for (int q = 0; q < 4; q++) {
                unsigned bq[4];
                ldsm4t(bq, W2base + (kk + (lane & 15)) * (W2C_STRIDE * 2)
                                 + (wn * 64 + q * 16) * 2 + ((lane >> 4) << 4));
                mma16816(accZ[2 * q],     a, bq[0], bq[1]);
                mma16816(accZ[2 * q + 1], a, bq[2], bq[3]);
            }
        }
        __syncthreads();                 // W2 buffer + Hc free
        if (nc < 7) { stage_w2(W2base, nc + 1, t); CP_COMMIT(); }  // overlaps next G1
    }

    // dump Z to smem (transpose buffer, stride 261) — zs aliases W1c (free now)
    float* zs = (float*)(sm + W1C_OFF);
#pragma unroll
    for (int q = 0; q < 8; q++) {
        int cc0 = wn * 64 + q * 8 + 2 * (lane & 3);
        int r   = m0 + (lane >> 2);
        zs[r * 261 + cc0]           = accZ[q][0];
        zs[r * 261 + cc0 + 1]       = accZ[q][1];
        zs[(r + 8) * 261 + cc0]     = accZ[q][2];
        zs[(r + 8) * 261 + cc0 + 1] = accZ[q][3];
    }
    __syncthreads();

    // epilogue: out = x + (z + b2) * gamma, float4-vectorized
    for (int i = t; i < 4096; i += NT) {
        int c = i >> 4, sub = i & 15;
        int rr = sub >> 1, half = sub & 1;
        int pp = rr * 8 + half * 4;
        float gm = __ldg(gamma + c), bb = __ldg(b2 + c);
        float4 z4;
        z4.x = (zs[(pp + 0) * 261 + c] + bb) * gm;
        z4.y = (zs[(pp + 1) * 261 + c] + bb) * gm;
        z4.z = (zs[(pp + 2) * 261 + c] + bb) * gm;
        z4.w = (zs[(pp + 3) * 261 + c] + bb) * gm;
        size_t g = (size_t)(c * HWD + h0 + rr) * HWD + w0;
        float4 xv = ((const float4*)(xb + g))[half];
        xv.x += z4.x; xv.y += z4.y; xv.z += z4.z; xv.w += z4.w;
        ((float4*)(ob + g))[half] = xv;
    }
}

extern "C" void kernel_launch(void* const* d_in, const int* in_sizes, int n_in,
                              void* d_out, int out_size) {
    const float* x     = (const float*)d_in[0];
    const int*   mask  = (const int*)d_in[1];
    const float* dw_w  = (const float*)d_in[2];
    const float* dw_b  = (const float*)d_in[3];
    const float* ln_w  = (const float*)d_in[4];
    const float* ln_b  = (const float*)d_in[5];
    const float* w1    = (const float*)d_in[6];
    const float* b1    = (const float*)d_in[7];
    const float* w2    = (const float*)d_in[8];
    const float* b2    = (const float*)d_in[9];
    const float* gamma = (const float*)d_in[10];
    float* out = (float*)d_out;

    convert_weights<<<512, 512>>>(w1, w2);

    cudaFuncSetAttribute(block_kernel,
                         cudaFuncAttributeMaxDynamicSharedMemorySize, SMEM_TOTAL);
    block_kernel<<<NBLK, NT, SMEM_TOTAL>>>(x, mask, dw_w, dw_b, ln_w, ln_b,
                                           b1, b2, gamma, out);
}